// round 11
// baseline (speedup 1.0000x reference)
#include <cuda_runtime.h>
#include <math.h>

#define Bc 4
#define Pc 12
#define Qc 12
#define Nc 2048
#define Dc 32
#define DAYSc 7
#define PBDc (Pc*Bc*Dc)   // 1536
#define BDc (Bc*Dc)       // 128
#define EMAX 128
#define NBLK 148
#define NT 1024

// ---------------- scratch (device globals; no allocation) ----------------
__device__ float g_ellv[Nc*EMAX];
__device__ int   g_elli[Nc*EMAX];
__device__ int   g_ellc[Nc];
__device__ float g_se[Nc*Dc];
__device__ float g_te[Bc*(Pc+Qc)*Dc];
__device__ float g_X0[Nc*PBDc];
__device__ float g_X1[Nc*PBDc];
__device__ float g_X2[Nc*PBDc];
__device__ float g_X3[Nc*PBDc];
__device__ float g_gpre[Pc*Bc*Nc*64];
__device__ float g_cpre[Pc*Bc*Nc*Dc];
__device__ float g_h [Nc*BDc];
__device__ float g_y1[Nc*BDc];
__device__ float g_y2[Nc*BDc];
__device__ float g_rh[Nc*BDc];
__device__ float g_u [Nc*BDc];
__device__ float g_Wgx[128*64];
__device__ float g_Wgh[128*64];
__device__ float g_Wcx[128*32];
__device__ float g_Wch[128*32];
// barrier words on SEPARATE 128B cache lines: arrivals RMW g_arrive,
// pollers read only g_release -> no strong-op serialization between them.
__device__ __align__(128) unsigned g_arrive[32];
__device__ __align__(128) unsigned g_release[32];

__device__ __forceinline__ float* buf_ptr(int s){
    switch(s){
        case 0: return g_X0; case 1: return g_X1; case 2: return g_X2; case 3: return g_X3;
    }
    return 0;
}

// ---------------- build ELL from dense L ----------------
__global__ void k_ell(const float* __restrict__ L){
    int row  = blockIdx.x*8 + (threadIdx.x>>5);
    int lane = threadIdx.x & 31;
    int cnt = 0;
    for(int c0=0;c0<Nc;c0+=32){
        float v = L[row*Nc + c0 + lane];
        unsigned m = __ballot_sync(0xffffffffu, v != 0.f);
        if(v != 0.f){
            int r = cnt + __popc(m & ((1u<<lane)-1u));
            if(r < EMAX){ g_elli[row*EMAX+r] = c0+lane; g_ellv[row*EMAX+r] = v; }
        }
        cnt += __popc(m);
    }
    if(lane==0) g_ellc[row] = cnt < EMAX ? cnt : EMAX;
}

// ---------------- reset barrier state ----------------
__global__ void k_reset(){
    if(threadIdx.x==0){ g_arrive[0] = 0u; g_release[0] = 0u; }
}

// ---------------- pack gate/cand weights ----------------
__global__ void k_pack(const float* __restrict__ Wg, const float* __restrict__ Wc){
    int i = blockIdx.x*blockDim.x + threadIdx.x;
    if(i < 128*64){
        int kd = i>>6, o = i&63; int k = kd>>5, d = kd&31;
        g_Wgx[i] = Wg[(k*64 + d)*64 + o];
        g_Wgh[i] = Wg[(k*64 + 32 + d)*64 + o];
    }
    if(i < 128*32){
        int kd = i>>5, o = i&31; int k = kd>>5, d = kd&31;
        g_Wcx[i] = Wc[(k*64 + d)*32 + o];
        g_Wch[i] = Wc[(k*64 + 32 + d)*32 + o];
    }
}

// ---------------- spatial embedding ----------------
__global__ void k_se(const float* __restrict__ SE, const float* __restrict__ W1,
                     const float* __restrict__ b1, const float* __restrict__ W2,
                     const float* __restrict__ b2){
    int n = blockIdx.x*8 + (threadIdx.x>>5);
    int lane = threadIdx.x & 31;
    float sein = SE[n*Dc + lane];
    float hid = b1[lane];
    #pragma unroll
    for(int d=0;d<32;d++) hid = fmaf(__shfl_sync(0xffffffffu, sein, d), W1[d*32+lane], hid);
    hid = fmaxf(hid, 0.f);
    float o = b2[lane];
    #pragma unroll
    for(int j=0;j<32;j++) o = fmaf(__shfl_sync(0xffffffffu, hid, j), W2[j*32+lane], o);
    g_se[n*Dc + lane] = o;
}

// ---------------- temporal embedding ----------------
__global__ void k_te(const int* __restrict__ TE, const float* __restrict__ W1,
                     const float* __restrict__ b1, const float* __restrict__ W2,
                     const float* __restrict__ b2){
    int bt = blockIdx.x;
    int lane = threadIdx.x;
    int day = TE[bt*2+0], tod = TE[bt*2+1];
    float hid = fmaxf(W1[day*32 + lane] + W1[(DAYSc+tod)*32 + lane] + b1[lane], 0.f);
    float o = b2[lane];
    #pragma unroll
    for(int j=0;j<32;j++) o = fmaf(__shfl_sync(0xffffffffu, hid, j), W2[j*32+lane], o);
    g_te[bt*32 + lane] = o;
}

// ---------------- input embedding + STE ----------------
__global__ void k_xembed(const float* __restrict__ X, const float* __restrict__ W1,
                         const float* __restrict__ b1, const float* __restrict__ W2,
                         const float* __restrict__ b2){
    int r = blockIdx.x*8 + (threadIdx.x>>5);
    int lane = threadIdx.x & 31;
    int tb = r >> 11, n = r & 2047;
    int t = tb / Bc, b = tb % Bc;
    float xv = X[(b*Pc + t)*Nc + n];
    float h1 = fmaxf(fmaf(xv, W1[lane], b1[lane]), 0.f);
    float o = b2[lane] + g_se[n*32 + lane] + g_te[(b*(Pc+Qc) + t)*32 + lane];
    #pragma unroll
    for(int j=0;j<32;j++) o = fmaf(__shfl_sync(0xffffffffu, h1, j), W2[j*32+lane], o);
    g_X0[n*PBDc + tb*32 + lane] = o;
}

// ---------------- big ELL SpMM (precompute, 1536 cols) ----------------
__global__ void k_spmm(int si_, int ss_, int so_, float alpha){
    const float* __restrict__ in  = buf_ptr(si_);
    const float* __restrict__ sub = (ss_ >= 0) ? buf_ptr(ss_) : 0;
    float* __restrict__ outp = buf_ptr(so_);
    int n = blockIdx.x;
    __shared__ float sv[EMAX];
    __shared__ int   sidx[EMAX];
    int cnt = g_ellc[n];
    for(int e=threadIdx.x; e<cnt; e+=blockDim.x){
        sv[e]   = g_ellv[n*EMAX + e];
        sidx[e] = g_elli[n*EMAX + e];
    }
    __syncthreads();
    for(int c=threadIdx.x; c<PBDc; c+=blockDim.x){
        float a0=0.f, a1=0.f;
        int e=0;
        for(; e+1<cnt; e+=2){
            a0 = fmaf(sv[e],   in[sidx[e]*PBDc + c],   a0);
            a1 = fmaf(sv[e+1], in[sidx[e+1]*PBDc + c], a1);
        }
        if(e<cnt) a0 = fmaf(sv[e], in[sidx[e]*PBDc + c], a0);
        float r = alpha*(a0+a1);
        if(sub) r -= sub[n*PBDc + c];
        outp[n*PBDc + c] = r;
    }
}

// ---------------- precompute gate_pre ----------------
__global__ __launch_bounds__(256) void k_pre_gate(const float* __restrict__ bg){
    int tb = blockIdx.y;
    int n0 = blockIdx.x*64;
    __shared__ float Ws[128*64];
    __shared__ float As[32*65];
    int tid = threadIdx.x;
    for(int i=tid;i<128*64;i+=256) Ws[i] = g_Wgx[i];
    int trow = tid>>4, tcol = tid&15;
    float acc[4][4];
    #pragma unroll
    for(int j=0;j<4;j++){ float bv = bg[tcol*4+j];
        #pragma unroll
        for(int i=0;i<4;i++) acc[i][j] = bv; }
    #pragma unroll
    for(int kk=0; kk<4; kk++){
        const float* __restrict__ Xa = buf_ptr(kk);
        __syncthreads();
        for(int i=tid; i<64*32; i+=256){
            int row = i>>5, k = i&31;
            As[k*65 + row] = Xa[(n0+row)*PBDc + tb*Dc + k];
        }
        __syncthreads();
        #pragma unroll
        for(int k=0;k<32;k++){
            float a0 = As[k*65 + trow*4 + 0];
            float a1 = As[k*65 + trow*4 + 1];
            float a2 = As[k*65 + trow*4 + 2];
            float a3 = As[k*65 + trow*4 + 3];
            float4 bv = *(const float4*)&Ws[(kk*32+k)*64 + tcol*4];
            acc[0][0]=fmaf(a0,bv.x,acc[0][0]); acc[0][1]=fmaf(a0,bv.y,acc[0][1]);
            acc[0][2]=fmaf(a0,bv.z,acc[0][2]); acc[0][3]=fmaf(a0,bv.w,acc[0][3]);
            acc[1][0]=fmaf(a1,bv.x,acc[1][0]); acc[1][1]=fmaf(a1,bv.y,acc[1][1]);
            acc[1][2]=fmaf(a1,bv.z,acc[1][2]); acc[1][3]=fmaf(a1,bv.w,acc[1][3]);
            acc[2][0]=fmaf(a2,bv.x,acc[2][0]); acc[2][1]=fmaf(a2,bv.y,acc[2][1]);
            acc[2][2]=fmaf(a2,bv.z,acc[2][2]); acc[2][3]=fmaf(a2,bv.w,acc[2][3]);
            acc[3][0]=fmaf(a3,bv.x,acc[3][0]); acc[3][1]=fmaf(a3,bv.y,acc[3][1]);
            acc[3][2]=fmaf(a3,bv.z,acc[3][2]); acc[3][3]=fmaf(a3,bv.w,acc[3][3]);
        }
    }
    #pragma unroll
    for(int i=0;i<4;i++){
        int n = n0 + trow*4 + i;
        #pragma unroll
        for(int j=0;j<4;j++)
            g_gpre[(tb*Nc + n)*64 + tcol*4 + j] = acc[i][j];
    }
}

// ---------------- precompute cand_pre ----------------
__global__ __launch_bounds__(256) void k_pre_cand(const float* __restrict__ bc){
    int tb = blockIdx.y;
    int n0 = blockIdx.x*64;
    __shared__ float Ws[128*32];
    __shared__ float As[32*65];
    int tid = threadIdx.x;
    for(int i=tid;i<128*32;i+=256) Ws[i] = g_Wcx[i];
    int trow = tid>>4, tcol = tid&15;
    float acc[4][2];
    #pragma unroll
    for(int j=0;j<2;j++){ float bv = bc[tcol*2+j];
        #pragma unroll
        for(int i=0;i<4;i++) acc[i][j] = bv; }
    #pragma unroll
    for(int kk=0; kk<4; kk++){
        const float* __restrict__ Xa = buf_ptr(kk);
        __syncthreads();
        for(int i=tid; i<64*32; i+=256){
            int row = i>>5, k = i&31;
            As[k*65 + row] = Xa[(n0+row)*PBDc + tb*Dc + k];
        }
        __syncthreads();
        #pragma unroll
        for(int k=0;k<32;k++){
            float a0 = As[k*65 + trow*4 + 0];
            float a1 = As[k*65 + trow*4 + 1];
            float a2 = As[k*65 + trow*4 + 2];
            float a3 = As[k*65 + trow*4 + 3];
            float b0 = Ws[(kk*32+k)*32 + tcol*2 + 0];
            float b1 = Ws[(kk*32+k)*32 + tcol*2 + 1];
            acc[0][0]=fmaf(a0,b0,acc[0][0]); acc[0][1]=fmaf(a0,b1,acc[0][1]);
            acc[1][0]=fmaf(a1,b0,acc[1][0]); acc[1][1]=fmaf(a1,b1,acc[1][1]);
            acc[2][0]=fmaf(a2,b0,acc[2][0]); acc[2][1]=fmaf(a2,b1,acc[2][1]);
            acc[3][0]=fmaf(a3,b0,acc[3][0]); acc[3][1]=fmaf(a3,b1,acc[3][1]);
        }
    }
    #pragma unroll
    for(int i=0;i<4;i++){
        int n = n0 + trow*4 + i;
        #pragma unroll
        for(int j=0;j<2;j++)
            g_cpre[(tb*Nc + n)*32 + tcol*2 + j] = acc[i][j];
    }
}

// ================= persistent recurrence kernel =================

// Two-word grid barrier: arrivals RMW g_arrive (acq_rel, with return);
// the last arriver publishes the epoch to g_release (separate line);
// everyone else polls g_release with acquire loads (read-only line -> no
// serialization against the arrival RMWs). Monotonic epochs, no reset.
__device__ __forceinline__ void gsync(unsigned &ep){
    __syncthreads();
    if(threadIdx.x==0){
        unsigned long long pa = __cvta_generic_to_global((void*)&g_arrive[0]);
        unsigned long long pr = __cvta_generic_to_global((void*)&g_release[0]);
        unsigned target = (ep + 1u) * (unsigned)NBLK;
        unsigned old;
        asm volatile("atom.acq_rel.gpu.global.add.u32 %0, [%1], %2;"
                     : "=r"(old) : "l"(pa), "r"(1u) : "memory");
        if(old == target - 1u){
            asm volatile("st.release.gpu.global.u32 [%0], %1;"
                         :: "l"(pr), "r"(ep + 1u) : "memory");
        }else{
            unsigned v;
            do{
                asm volatile("ld.acquire.gpu.global.u32 %0, [%1];"
                             : "=r"(v) : "l"(pr) : "memory");
            }while(v < ep + 1u);
        }
    }
    __syncthreads();
    ep += 1u;
}

// SpMM over 128-col state: out = alpha*(L@in) - sub   (full grid, NT threads)
__device__ __forceinline__ void spmm_phase(const float* __restrict__ in,
                                           const float* __restrict__ sub,
                                           float* __restrict__ out, float alpha){
    for(int pos = blockIdx.x*NT + threadIdx.x; pos < Nc*BDc; pos += NBLK*NT){
        int n = pos>>7, c = pos&127;
        int cnt = g_ellc[n];
        const float* ev = g_ellv + n*EMAX;
        const int*   ei = g_elli + n*EMAX;
        float a0=0.f,a1=0.f,a2=0.f,a3=0.f;
        int e=0;
        for(; e+3<cnt; e+=4){
            a0 = fmaf(ev[e],   in[ei[e]*BDc + c],   a0);
            a1 = fmaf(ev[e+1], in[ei[e+1]*BDc + c], a1);
            a2 = fmaf(ev[e+2], in[ei[e+2]*BDc + c], a2);
            a3 = fmaf(ev[e+3], in[ei[e+3]*BDc + c], a3);
        }
        for(; e<cnt; e++) a0 = fmaf(ev[e], in[ei[e]*BDc + c], a0);
        float r = alpha*((a0+a1)+(a2+a3));
        if(sub) r -= sub[n*BDc + c];
        out[n*BDc + c] = r;
    }
}

// stage A: build transposed smem tiles for 3 basis arrays + compute 4th (Cheb hop)
__device__ __forceinline__ void stageA(float* As, int n0,
                                       const float* __restrict__ t0,
                                       const float* __restrict__ t1,
                                       const float* __restrict__ t2){
    for(int i2 = threadIdx.x; i2 < 2048; i2 += NT){
        int nl = i2>>7, j = i2&127;
        int nn = n0 + nl;
        int dst = (j&31)*65 + nl*4 + (j>>5);
        As[0*2080 + dst] = t0[nn*BDc + j];
        float v1 = t1[nn*BDc + j];
        As[1*2080 + dst] = v1;
        As[2*2080 + dst] = t2[nn*BDc + j];
        // t3 = 2*L*t2 - t1 (in-tile Chebyshev hop)
        int cnt = g_ellc[nn];
        const float* ev = g_ellv + nn*EMAX;
        const int*   ei = g_elli + nn*EMAX;
        float a0=0.f,a1=0.f,a2=0.f,a3=0.f;
        int e=0;
        for(; e+3<cnt; e+=4){
            a0 = fmaf(ev[e],   t2[ei[e]*BDc + j],   a0);
            a1 = fmaf(ev[e+1], t2[ei[e+1]*BDc + j], a1);
            a2 = fmaf(ev[e+2], t2[ei[e+2]*BDc + j], a2);
            a3 = fmaf(ev[e+3], t2[ei[e+3]*BDc + j], a3);
        }
        for(; e<cnt; e++) a0 = fmaf(ev[e], t2[ei[e]*BDc + j], a0);
        As[3*2080 + dst] = 2.f*((a0+a1)+(a2+a3)) - v1;
    }
}

__global__ __launch_bounds__(NT) void k_recur(const float* __restrict__ Wo1,
                                              const float* __restrict__ bo1,
                                              const float* __restrict__ Wo2,
                                              const float* __restrict__ bo2,
                                              float* __restrict__ out){
    extern __shared__ float sm[];
    float* Wg = sm;            // 8192 floats (32 KB)
    float* Wc = sm + 8192;     // 4096 floats (16 KB)
    float* As = sm + 12288;    // 4*2080 floats (33.3 KB)
    int tid = threadIdx.x;
    int bid = blockIdx.x;
    unsigned ep = 0u;

    // load recurrent weights into smem once (persist across all steps)
    for(int i=tid;i<8192;i+=NT) Wg[i] = g_Wgh[i];
    for(int i=tid;i<4096;i+=NT) Wc[i] = g_Wch[i];

    // ---- step 0: h = (1-sigmoid(gpre_u)) * tanh(cpre) ----
    for(int idx = bid*NT + tid; idx < Nc*BDc; idx += NBLK*NT){
        int n = idx>>7, j = idx&127, b = j>>5, d = j&31;
        float u = 1.f/(1.f + expf(-g_gpre[(b*Nc + n)*64 + 32 + d]));
        float c = tanhf(g_cpre[(b*Nc + n)*32 + d]);
        g_h[idx] = (1.f - u)*c;
    }
    gsync(ep);

    for(int t=1; t<Pc; t++){
        // ---- y1 = L h ----
        spmm_phase(g_h, 0, g_y1, 1.f);
        gsync(ep);
        // ---- y2 = 2 L y1 - h ----
        spmm_phase(g_y1, g_h, g_y2, 2.f);
        gsync(ep);
        // ---- gate phase: stage A (tiles + y3), stage B (GEMM+sigmoid) ----
        if(bid < 128){
            int n0 = bid*16;
            stageA(As, n0, g_h, g_y1, g_y2);
            __syncthreads();
            if(tid < 256){
                int trow = tid>>4, tcol = tid&15;
                int n = n0 + trow;
                float acc[4][4];
                #pragma unroll
                for(int i=0;i<4;i++)
                    #pragma unroll
                    for(int j=0;j<4;j++)
                        acc[i][j] = g_gpre[((t*Bc + i)*Nc + n)*64 + tcol*4 + j];
                #pragma unroll
                for(int seg=0; seg<4; seg++){
                    const float* Aseg = As + seg*2080;
                    #pragma unroll
                    for(int k=0;k<32;k++){
                        float a0 = Aseg[k*65 + trow*4 + 0];
                        float a1 = Aseg[k*65 + trow*4 + 1];
                        float a2 = Aseg[k*65 + trow*4 + 2];
                        float a3 = Aseg[k*65 + trow*4 + 3];
                        float4 bv = *(const float4*)&Wg[(seg*32+k)*64 + tcol*4];
                        acc[0][0]=fmaf(a0,bv.x,acc[0][0]); acc[0][1]=fmaf(a0,bv.y,acc[0][1]);
                        acc[0][2]=fmaf(a0,bv.z,acc[0][2]); acc[0][3]=fmaf(a0,bv.w,acc[0][3]);
                        acc[1][0]=fmaf(a1,bv.x,acc[1][0]); acc[1][1]=fmaf(a1,bv.y,acc[1][1]);
                        acc[1][2]=fmaf(a1,bv.z,acc[1][2]); acc[1][3]=fmaf(a1,bv.w,acc[1][3]);
                        acc[2][0]=fmaf(a2,bv.x,acc[2][0]); acc[2][1]=fmaf(a2,bv.y,acc[2][1]);
                        acc[2][2]=fmaf(a2,bv.z,acc[2][2]); acc[2][3]=fmaf(a2,bv.w,acc[2][3]);
                        acc[3][0]=fmaf(a3,bv.x,acc[3][0]); acc[3][1]=fmaf(a3,bv.y,acc[3][1]);
                        acc[3][2]=fmaf(a3,bv.z,acc[3][2]); acc[3][3]=fmaf(a3,bv.w,acc[3][3]);
                    }
                }
                #pragma unroll
                for(int i=0;i<4;i++){
                    #pragma unroll
                    for(int j=0;j<4;j++){
                        int o = tcol*4 + j;
                        float v = 1.f/(1.f + expf(-acc[i][j]));
                        int addr = n*BDc + i*32 + (o&31);
                        if(o < 32) g_rh[addr] = v * g_h[addr];
                        else       g_u[addr]  = v;
                    }
                }
            }
        }
        gsync(ep);
        // ---- z1 = L rh ----
        spmm_phase(g_rh, 0, g_y1, 1.f);
        gsync(ep);
        // ---- z2 = 2 L z1 - rh ----
        spmm_phase(g_y1, g_rh, g_y2, 2.f);
        gsync(ep);
        // ---- cand phase: stage A (tiles + z3), stage B (GEMM+tanh+update) ----
        if(bid < 128){
            int n0 = bid*16;
            stageA(As, n0, g_rh, g_y1, g_y2);
            __syncthreads();
            if(tid < 256){
                int trow = tid>>4, tcol = tid&15;
                int n = n0 + trow;
                float acc[4][2];
                #pragma unroll
                for(int i=0;i<4;i++)
                    #pragma unroll
                    for(int j=0;j<2;j++)
                        acc[i][j] = g_cpre[((t*Bc + i)*Nc + n)*32 + tcol*2 + j];
                #pragma unroll
                for(int seg=0; seg<4; seg++){
                    const float* Aseg = As + seg*2080;
                    #pragma unroll
                    for(int k=0;k<32;k++){
                        float a0 = Aseg[k*65 + trow*4 + 0];
                        float a1 = Aseg[k*65 + trow*4 + 1];
                        float a2 = Aseg[k*65 + trow*4 + 2];
                        float a3 = Aseg[k*65 + trow*4 + 3];
                        float b0 = Wc[(seg*32+k)*32 + tcol*2 + 0];
                        float b1 = Wc[(seg*32+k)*32 + tcol*2 + 1];
                        acc[0][0]=fmaf(a0,b0,acc[0][0]); acc[0][1]=fmaf(a0,b1,acc[0][1]);
                        acc[1][0]=fmaf(a1,b0,acc[1][0]); acc[1][1]=fmaf(a1,b1,acc[1][1]);
                        acc[2][0]=fmaf(a2,b0,acc[2][0]); acc[2][1]=fmaf(a2,b1,acc[2][1]);
                        acc[3][0]=fmaf(a3,b0,acc[3][0]); acc[3][1]=fmaf(a3,b1,acc[3][1]);
                    }
                }
                #pragma unroll
                for(int i=0;i<4;i++){
                    #pragma unroll
                    for(int j=0;j<2;j++){
                        int o = tcol*2 + j;
                        int addr = n*BDc + i*32 + o;
                        float c = tanhf(acc[i][j]);
                        float u = g_u[addr];
                        float h = g_h[addr];
                        g_h[addr] = u*h + (1.f - u)*c;
                    }
                }
            }
        }
        gsync(ep);
    }

    // ---- output head: y = relu(h W1 + b1) W2 + b2, transposed store ----
    {
        int lane = tid & 31;
        for(int r = bid*32 + (tid>>5); r < Bc*Nc; r += NBLK*32){
            int b = r>>11, n = r&2047;
            float hv = g_h[n*BDc + b*Dc + lane];
            float hid = bo1[lane];
            #pragma unroll
            for(int j=0;j<32;j++) hid = fmaf(__shfl_sync(0xffffffffu, hv, j), Wo1[j*32+lane], hid);
            hid = fmaxf(hid, 0.f);
            float o = (lane < Qc) ? bo2[lane] : 0.f;
            #pragma unroll
            for(int d=0;d<32;d++){
                float s = __shfl_sync(0xffffffffu, hid, d);
                if(lane < Qc) o = fmaf(s, Wo2[d*Qc + lane], o);
            }
            if(lane < Qc) out[(b*Qc + lane)*Nc + n] = o;
        }
    }
}

// ---------------- launcher ----------------
extern "C" void kernel_launch(void* const* d_in, const int* in_sizes, int n_in,
                              void* d_out, int out_size){
    const float* X     = (const float*)d_in[0];
    const int*   TE    = (const int*)  d_in[1];
    const float* L     = (const float*)d_in[2];
    const float* SE    = (const float*)d_in[3];
    const float* W_se1 = (const float*)d_in[4];  const float* b_se1 = (const float*)d_in[5];
    const float* W_se2 = (const float*)d_in[6];  const float* b_se2 = (const float*)d_in[7];
    const float* W_te1 = (const float*)d_in[8];  const float* b_te1 = (const float*)d_in[9];
    const float* W_te2 = (const float*)d_in[10]; const float* b_te2 = (const float*)d_in[11];
    const float* W_in1 = (const float*)d_in[12]; const float* b_in1 = (const float*)d_in[13];
    const float* W_in2 = (const float*)d_in[14]; const float* b_in2 = (const float*)d_in[15];
    const float* W_gate= (const float*)d_in[16];
    const float* b_gate= (const float*)d_in[17];
    const float* W_cand= (const float*)d_in[18];
    const float* b_cand= (const float*)d_in[19];
    const float* W_out1= (const float*)d_in[20]; const float* b_out1= (const float*)d_in[21];
    const float* W_out2= (const float*)d_in[22]; const float* b_out2= (const float*)d_in[23];
    float* out = (float*)d_out;

    const int smem_recur = (8192 + 4096 + 4*2080) * 4;   // 82432 B
    cudaFuncSetAttribute(k_recur, cudaFuncAttributeMaxDynamicSharedMemorySize, smem_recur);

    k_reset<<<1, 32>>>();
    k_ell<<<Nc/8, 256>>>(L);
    k_pack<<<32, 256>>>(W_gate, W_cand);
    k_se<<<Nc/8, 256>>>(SE, W_se1, b_se1, W_se2, b_se2);
    k_te<<<Bc*(Pc+Qc), 32>>>(TE, W_te1, b_te1, W_te2, b_te2);
    k_xembed<<<(Pc*Bc*Nc)/8, 256>>>(X, W_in1, b_in1, W_in2, b_in2);

    // Chebyshev polys of x for all timesteps (1536 columns)
    k_spmm<<<Nc, 256>>>(0, -1, 1, 1.f);   // X1 = L X0
    k_spmm<<<Nc, 256>>>(1,  0, 2, 2.f);   // X2 = 2 L X1 - X0
    k_spmm<<<Nc, 256>>>(2,  1, 3, 2.f);   // X3 = 2 L X2 - X1

    dim3 pg(32, Pc*Bc);
    k_pre_gate<<<pg, 256>>>(b_gate);
    k_pre_cand<<<pg, 256>>>(b_cand);

    // whole recurrence + step0 + output head in one persistent kernel
    k_recur<<<NBLK, NT, smem_recur>>>(W_out1, b_out1, W_out2, b_out2, out);
}

// round 12
// speedup vs baseline: 1.6118x; 1.6118x over previous
#include <cuda_runtime.h>
#include <math.h>

#define Bc 4
#define Pc 12
#define Qc 12
#define Nc 2048
#define Dc 32
#define DAYSc 7
#define PBDc (Pc*Bc*Dc)   // 1536
#define BDc (Bc*Dc)       // 128
#define EMAX 128

// ---------------- scratch (device globals; no allocation) ----------------
__device__ float g_ellv[Nc*EMAX];
__device__ int   g_elli[Nc*EMAX];
__device__ int   g_ellc[Nc];
__device__ float g_se[Nc*Dc];
__device__ float g_te[Bc*(Pc+Qc)*Dc];
__device__ float g_X0[Nc*PBDc];
__device__ float g_X1[Nc*PBDc];
__device__ float g_X2[Nc*PBDc];
__device__ float g_X3[Nc*PBDc];
__device__ float g_gpre[Pc*Bc*Nc*64];
__device__ float g_cpre[Pc*Bc*Nc*Dc];
__device__ float g_h [Nc*BDc];
__device__ float g_y1[Nc*BDc];
__device__ float g_y2[Nc*BDc];
__device__ float g_rh[Nc*BDc];
__device__ float g_u [Nc*BDc];
__device__ float g_Wgx[128*64];
__device__ float g_Wgh[128*64];
__device__ float g_Wcx[128*32];
__device__ float g_Wch[128*32];

__device__ __forceinline__ float* buf_ptr(int s){
    switch(s){
        case 0: return g_X0; case 1: return g_X1; case 2: return g_X2; case 3: return g_X3;
    }
    return 0;
}
__device__ __forceinline__ float* sbuf_ptr(int s){
    switch(s){
        case 0: return g_h; case 1: return g_y1; case 2: return g_y2; case 3: return g_rh;
    }
    return 0;
}

// fast activations: tanh.approx.f32 (1 MUFU), sigmoid via tanh (division-free)
__device__ __forceinline__ float ftanh(float x){
    float t; asm("tanh.approx.f32 %0, %1;" : "=f"(t) : "f"(x)); return t;
}
__device__ __forceinline__ float fsig(float x){
    float t; asm("tanh.approx.f32 %0, %1;" : "=f"(t) : "f"(0.5f*x));
    return fmaf(0.5f, t, 0.5f);
}

// ---------------- build ELL from dense L ----------------
__global__ void k_ell(const float* __restrict__ L){
    int row  = blockIdx.x*8 + (threadIdx.x>>5);
    int lane = threadIdx.x & 31;
    int cnt = 0;
    for(int c0=0;c0<Nc;c0+=32){
        float v = L[row*Nc + c0 + lane];
        unsigned m = __ballot_sync(0xffffffffu, v != 0.f);
        if(v != 0.f){
            int r = cnt + __popc(m & ((1u<<lane)-1u));
            if(r < EMAX){ g_elli[row*EMAX+r] = c0+lane; g_ellv[row*EMAX+r] = v; }
        }
        cnt += __popc(m);
    }
    if(lane==0) g_ellc[row] = cnt < EMAX ? cnt : EMAX;
}

// ---------------- pack gate/cand weights ----------------
__global__ void k_pack(const float* __restrict__ Wg, const float* __restrict__ Wc){
    int i = blockIdx.x*blockDim.x + threadIdx.x;
    if(i < 128*64){
        int kd = i>>6, o = i&63; int k = kd>>5, d = kd&31;
        g_Wgx[i] = Wg[(k*64 + d)*64 + o];
        g_Wgh[i] = Wg[(k*64 + 32 + d)*64 + o];
    }
    if(i < 128*32){
        int kd = i>>5, o = i&31; int k = kd>>5, d = kd&31;
        g_Wcx[i] = Wc[(k*64 + d)*32 + o];
        g_Wch[i] = Wc[(k*64 + 32 + d)*32 + o];
    }
}

// ---------------- spatial embedding ----------------
__global__ void k_se(const float* __restrict__ SE, const float* __restrict__ W1,
                     const float* __restrict__ b1, const float* __restrict__ W2,
                     const float* __restrict__ b2){
    int n = blockIdx.x*8 + (threadIdx.x>>5);
    int lane = threadIdx.x & 31;
    float sein = SE[n*Dc + lane];
    float hid = b1[lane];
    #pragma unroll
    for(int d=0;d<32;d++) hid = fmaf(__shfl_sync(0xffffffffu, sein, d), W1[d*32+lane], hid);
    hid = fmaxf(hid, 0.f);
    float o = b2[lane];
    #pragma unroll
    for(int j=0;j<32;j++) o = fmaf(__shfl_sync(0xffffffffu, hid, j), W2[j*32+lane], o);
    g_se[n*Dc + lane] = o;
}

// ---------------- temporal embedding ----------------
__global__ void k_te(const int* __restrict__ TE, const float* __restrict__ W1,
                     const float* __restrict__ b1, const float* __restrict__ W2,
                     const float* __restrict__ b2){
    int bt = blockIdx.x;
    int lane = threadIdx.x;
    int day = TE[bt*2+0], tod = TE[bt*2+1];
    float hid = fmaxf(W1[day*32 + lane] + W1[(DAYSc+tod)*32 + lane] + b1[lane], 0.f);
    float o = b2[lane];
    #pragma unroll
    for(int j=0;j<32;j++) o = fmaf(__shfl_sync(0xffffffffu, hid, j), W2[j*32+lane], o);
    g_te[bt*32 + lane] = o;
}

// ---------------- input embedding + STE ----------------
__global__ void k_xembed(const float* __restrict__ X, const float* __restrict__ W1,
                         const float* __restrict__ b1, const float* __restrict__ W2,
                         const float* __restrict__ b2){
    int r = blockIdx.x*8 + (threadIdx.x>>5);
    int lane = threadIdx.x & 31;
    int tb = r >> 11, n = r & 2047;
    int t = tb / Bc, b = tb % Bc;
    float xv = X[(b*Pc + t)*Nc + n];
    float h1 = fmaxf(fmaf(xv, W1[lane], b1[lane]), 0.f);
    float o = b2[lane] + g_se[n*32 + lane] + g_te[(b*(Pc+Qc) + t)*32 + lane];
    #pragma unroll
    for(int j=0;j<32;j++) o = fmaf(__shfl_sync(0xffffffffu, h1, j), W2[j*32+lane], o);
    g_X0[n*PBDc + tb*32 + lane] = o;
}

// ---------------- big ELL SpMM (precompute, 1536 cols, float4) ----------------
__global__ void k_spmm(int si_, int ss_, int so_, float alpha){
    const float* in  = buf_ptr(si_);
    const float* sub = (ss_ >= 0) ? buf_ptr(ss_) : 0;
    float* outp = buf_ptr(so_);
    int n = blockIdx.x;
    __shared__ float sv[EMAX];
    __shared__ int   sidx[EMAX];
    int cnt = g_ellc[n];
    for(int e=threadIdx.x; e<cnt; e+=blockDim.x){
        sv[e]   = g_ellv[n*EMAX + e];
        sidx[e] = g_elli[n*EMAX + e];
    }
    __syncthreads();
    const float4* in4 = (const float4*)in;
    for(int q=threadIdx.x; q<PBDc/4; q+=blockDim.x){
        float4 a = {0.f,0.f,0.f,0.f}, b = {0.f,0.f,0.f,0.f};
        int e=0;
        for(; e+1<cnt; e+=2){
            float v0 = sv[e], v1 = sv[e+1];
            float4 x0 = in4[sidx[e]*(PBDc/4) + q];
            float4 x1 = in4[sidx[e+1]*(PBDc/4) + q];
            a.x=fmaf(v0,x0.x,a.x); a.y=fmaf(v0,x0.y,a.y); a.z=fmaf(v0,x0.z,a.z); a.w=fmaf(v0,x0.w,a.w);
            b.x=fmaf(v1,x1.x,b.x); b.y=fmaf(v1,x1.y,b.y); b.z=fmaf(v1,x1.z,b.z); b.w=fmaf(v1,x1.w,b.w);
        }
        if(e<cnt){
            float v0 = sv[e];
            float4 x0 = in4[sidx[e]*(PBDc/4) + q];
            a.x=fmaf(v0,x0.x,a.x); a.y=fmaf(v0,x0.y,a.y); a.z=fmaf(v0,x0.z,a.z); a.w=fmaf(v0,x0.w,a.w);
        }
        float4 r;
        r.x = alpha*(a.x+b.x); r.y = alpha*(a.y+b.y); r.z = alpha*(a.z+b.z); r.w = alpha*(a.w+b.w);
        if(sub){
            float4 s = ((const float4*)sub)[n*(PBDc/4) + q];
            r.x -= s.x; r.y -= s.y; r.z -= s.z; r.w -= s.w;
        }
        ((float4*)outp)[n*(PBDc/4) + q] = r;
    }
}

// ---------------- precompute gate_pre ----------------
__global__ __launch_bounds__(256) void k_pre_gate(const float* __restrict__ bg){
    int tb = blockIdx.y;
    int n0 = blockIdx.x*64;
    __shared__ float Ws[128*64];
    __shared__ float As[32*65];
    int tid = threadIdx.x;
    for(int i=tid;i<128*64;i+=256) Ws[i] = g_Wgx[i];
    int trow = tid>>4, tcol = tid&15;
    float acc[4][4];
    #pragma unroll
    for(int j=0;j<4;j++){ float bv = bg[tcol*4+j];
        #pragma unroll
        for(int i=0;i<4;i++) acc[i][j] = bv; }
    #pragma unroll
    for(int kk=0; kk<4; kk++){
        const float* __restrict__ Xa = buf_ptr(kk);
        __syncthreads();
        for(int i=tid; i<512; i+=256){
            int row = i>>3, q = i&7;
            float4 x = *(const float4*)&Xa[(n0+row)*PBDc + tb*Dc + q*4];
            As[(4*q+0)*65 + row] = x.x;
            As[(4*q+1)*65 + row] = x.y;
            As[(4*q+2)*65 + row] = x.z;
            As[(4*q+3)*65 + row] = x.w;
        }
        __syncthreads();
        #pragma unroll
        for(int k=0;k<32;k++){
            float a0 = As[k*65 + trow*4 + 0];
            float a1 = As[k*65 + trow*4 + 1];
            float a2 = As[k*65 + trow*4 + 2];
            float a3 = As[k*65 + trow*4 + 3];
            float4 bv = *(const float4*)&Ws[(kk*32+k)*64 + tcol*4];
            acc[0][0]=fmaf(a0,bv.x,acc[0][0]); acc[0][1]=fmaf(a0,bv.y,acc[0][1]);
            acc[0][2]=fmaf(a0,bv.z,acc[0][2]); acc[0][3]=fmaf(a0,bv.w,acc[0][3]);
            acc[1][0]=fmaf(a1,bv.x,acc[1][0]); acc[1][1]=fmaf(a1,bv.y,acc[1][1]);
            acc[1][2]=fmaf(a1,bv.z,acc[1][2]); acc[1][3]=fmaf(a1,bv.w,acc[1][3]);
            acc[2][0]=fmaf(a2,bv.x,acc[2][0]); acc[2][1]=fmaf(a2,bv.y,acc[2][1]);
            acc[2][2]=fmaf(a2,bv.z,acc[2][2]); acc[2][3]=fmaf(a2,bv.w,acc[2][3]);
            acc[3][0]=fmaf(a3,bv.x,acc[3][0]); acc[3][1]=fmaf(a3,bv.y,acc[3][1]);
            acc[3][2]=fmaf(a3,bv.z,acc[3][2]); acc[3][3]=fmaf(a3,bv.w,acc[3][3]);
        }
    }
    #pragma unroll
    for(int i=0;i<4;i++){
        int n = n0 + trow*4 + i;
        #pragma unroll
        for(int j=0;j<4;j++)
            g_gpre[(tb*Nc + n)*64 + tcol*4 + j] = acc[i][j];
    }
}

// ---------------- precompute cand_pre ----------------
__global__ __launch_bounds__(256) void k_pre_cand(const float* __restrict__ bc){
    int tb = blockIdx.y;
    int n0 = blockIdx.x*64;
    __shared__ float Ws[128*32];
    __shared__ float As[32*65];
    int tid = threadIdx.x;
    for(int i=tid;i<128*32;i+=256) Ws[i] = g_Wcx[i];
    int trow = tid>>4, tcol = tid&15;
    float acc[4][2];
    #pragma unroll
    for(int j=0;j<2;j++){ float bv = bc[tcol*2+j];
        #pragma unroll
        for(int i=0;i<4;i++) acc[i][j] = bv; }
    #pragma unroll
    for(int kk=0; kk<4; kk++){
        const float* __restrict__ Xa = buf_ptr(kk);
        __syncthreads();
        for(int i=tid; i<512; i+=256){
            int row = i>>3, q = i&7;
            float4 x = *(const float4*)&Xa[(n0+row)*PBDc + tb*Dc + q*4];
            As[(4*q+0)*65 + row] = x.x;
            As[(4*q+1)*65 + row] = x.y;
            As[(4*q+2)*65 + row] = x.z;
            As[(4*q+3)*65 + row] = x.w;
        }
        __syncthreads();
        #pragma unroll
        for(int k=0;k<32;k++){
            float a0 = As[k*65 + trow*4 + 0];
            float a1 = As[k*65 + trow*4 + 1];
            float a2 = As[k*65 + trow*4 + 2];
            float a3 = As[k*65 + trow*4 + 3];
            float b0 = Ws[(kk*32+k)*32 + tcol*2 + 0];
            float b1 = Ws[(kk*32+k)*32 + tcol*2 + 1];
            acc[0][0]=fmaf(a0,b0,acc[0][0]); acc[0][1]=fmaf(a0,b1,acc[0][1]);
            acc[1][0]=fmaf(a1,b0,acc[1][0]); acc[1][1]=fmaf(a1,b1,acc[1][1]);
            acc[2][0]=fmaf(a2,b0,acc[2][0]); acc[2][1]=fmaf(a2,b1,acc[2][1]);
            acc[3][0]=fmaf(a3,b0,acc[3][0]); acc[3][1]=fmaf(a3,b1,acc[3][1]);
        }
    }
    #pragma unroll
    for(int i=0;i<4;i++){
        int n = n0 + trow*4 + i;
        #pragma unroll
        for(int j=0;j<2;j++)
            g_cpre[(tb*Nc + n)*32 + tcol*2 + j] = acc[i][j];
    }
}

// ---------------- step 0 ----------------
__global__ void k_step0(){
    int idx = blockIdx.x*blockDim.x + threadIdx.x;   // over Nc*BDc
    int n = idx>>7, j = idx&127, b = j>>5, d = j&31;
    float u = fsig(g_gpre[(b*Nc + n)*64 + 32 + d]);
    float c = ftanh(g_cpre[(b*Nc + n)*32 + d]);
    g_h[idx] = (1.f - u)*c;
}

// ---------------- recurrent SpMM (128 cols, float4 + int4 ELL) ----------------
__global__ __launch_bounds__(256) void k_spmm4(int si_, int ss_, int so_, float alpha){
    const float4* in4  = (const float4*)sbuf_ptr(si_);
    const float4* sub4 = (ss_ >= 0) ? (const float4*)sbuf_ptr(ss_) : 0;
    float4* out4 = (float4*)sbuf_ptr(so_);
    int i = blockIdx.x*256 + threadIdx.x;   // < Nc*32
    int n = i>>5, q = i&31;
    int cnt = g_ellc[n];
    const float4* ev4 = (const float4*)(g_ellv + n*EMAX);
    const int4*   ei4 = (const int4*)(g_elli + n*EMAX);
    float4 a = {0.f,0.f,0.f,0.f}, b = {0.f,0.f,0.f,0.f};
    int nIt = cnt>>2;
    for(int e4=0; e4<nIt; e4++){
        float4 v = ev4[e4]; int4 ix = ei4[e4];
        float4 x0 = in4[ix.x*32 + q];
        float4 x1 = in4[ix.y*32 + q];
        float4 x2 = in4[ix.z*32 + q];
        float4 x3 = in4[ix.w*32 + q];
        a.x=fmaf(v.x,x0.x,a.x); a.y=fmaf(v.x,x0.y,a.y); a.z=fmaf(v.x,x0.z,a.z); a.w=fmaf(v.x,x0.w,a.w);
        b.x=fmaf(v.y,x1.x,b.x); b.y=fmaf(v.y,x1.y,b.y); b.z=fmaf(v.y,x1.z,b.z); b.w=fmaf(v.y,x1.w,b.w);
        a.x=fmaf(v.z,x2.x,a.x); a.y=fmaf(v.z,x2.y,a.y); a.z=fmaf(v.z,x2.z,a.z); a.w=fmaf(v.z,x2.w,a.w);
        b.x=fmaf(v.w,x3.x,b.x); b.y=fmaf(v.w,x3.y,b.y); b.z=fmaf(v.w,x3.z,b.z); b.w=fmaf(v.w,x3.w,b.w);
    }
    for(int e=nIt*4; e<cnt; e++){
        float v = g_ellv[n*EMAX+e];
        float4 x = in4[g_elli[n*EMAX+e]*32 + q];
        a.x=fmaf(v,x.x,a.x); a.y=fmaf(v,x.y,a.y); a.z=fmaf(v,x.z,a.z); a.w=fmaf(v,x.w,a.w);
    }
    float4 r;
    r.x = alpha*(a.x+b.x); r.y = alpha*(a.y+b.y); r.z = alpha*(a.z+b.z); r.w = alpha*(a.w+b.w);
    if(sub4){
        float4 s = sub4[n*32 + q];
        r.x -= s.x; r.y -= s.y; r.z -= s.z; r.w -= s.w;
    }
    out4[n*32 + q] = r;
}

// ---------------- gate: fused y3 hop + GEMM + sigmoid ----------------
__global__ __launch_bounds__(512) void k_gate(int t){
    extern __shared__ float sm[];
    float* Ws = sm;            // 8192 floats
    float* As = sm + 8192;     // 4*2080 floats
    int tid = threadIdx.x;
    int n0 = blockIdx.x*16;
    for(int i=tid;i<8192;i+=512) Ws[i] = g_Wgh[i];
    // ---- stage A: 16 rows x 32 float4 cols, y3 computed in-tile ----
    {
        int nl = tid>>5, q = tid&31;
        int nn = n0 + nl;
        const float4* h4  = (const float4*)g_h;
        const float4* y14 = (const float4*)g_y1;
        const float4* y24 = (const float4*)g_y2;
        float4 v0 = h4[nn*32+q];
        float4 v1 = y14[nn*32+q];
        float4 v2 = y24[nn*32+q];
        int cnt = g_ellc[nn];
        const float4* ev4 = (const float4*)(g_ellv + nn*EMAX);
        const int4*   ei4 = (const int4*)(g_elli + nn*EMAX);
        float4 a = {0.f,0.f,0.f,0.f}, b = {0.f,0.f,0.f,0.f};
        int nIt = cnt>>2;
        for(int e4=0; e4<nIt; e4++){
            float4 v = ev4[e4]; int4 ix = ei4[e4];
            float4 x0 = y24[ix.x*32+q];
            float4 x1 = y24[ix.y*32+q];
            float4 x2 = y24[ix.z*32+q];
            float4 x3 = y24[ix.w*32+q];
            a.x=fmaf(v.x,x0.x,a.x); a.y=fmaf(v.x,x0.y,a.y); a.z=fmaf(v.x,x0.z,a.z); a.w=fmaf(v.x,x0.w,a.w);
            b.x=fmaf(v.y,x1.x,b.x); b.y=fmaf(v.y,x1.y,b.y); b.z=fmaf(v.y,x1.z,b.z); b.w=fmaf(v.y,x1.w,b.w);
            a.x=fmaf(v.z,x2.x,a.x); a.y=fmaf(v.z,x2.y,a.y); a.z=fmaf(v.z,x2.z,a.z); a.w=fmaf(v.z,x2.w,a.w);
            b.x=fmaf(v.w,x3.x,b.x); b.y=fmaf(v.w,x3.y,b.y); b.z=fmaf(v.w,x3.z,b.z); b.w=fmaf(v.w,x3.w,b.w);
        }
        for(int e=nIt*4; e<cnt; e++){
            float v = g_ellv[nn*EMAX+e];
            float4 x = y24[g_elli[nn*EMAX+e]*32+q];
            a.x=fmaf(v,x.x,a.x); a.y=fmaf(v,x.y,a.y); a.z=fmaf(v,x.z,a.z); a.w=fmaf(v,x.w,a.w);
        }
        float4 v3;
        v3.x = 2.f*(a.x+b.x) - v1.x;
        v3.y = 2.f*(a.y+b.y) - v1.y;
        v3.z = 2.f*(a.z+b.z) - v1.z;
        v3.w = 2.f*(a.w+b.w) - v1.w;
        int c0 = 4*q;
        int base = nl*4 + (c0>>5);
        int k0 = c0 & 31;
        As[0*2080 + (k0+0)*65 + base] = v0.x; As[0*2080 + (k0+1)*65 + base] = v0.y;
        As[0*2080 + (k0+2)*65 + base] = v0.z; As[0*2080 + (k0+3)*65 + base] = v0.w;
        As[1*2080 + (k0+0)*65 + base] = v1.x; As[1*2080 + (k0+1)*65 + base] = v1.y;
        As[1*2080 + (k0+2)*65 + base] = v1.z; As[1*2080 + (k0+3)*65 + base] = v1.w;
        As[2*2080 + (k0+0)*65 + base] = v2.x; As[2*2080 + (k0+1)*65 + base] = v2.y;
        As[2*2080 + (k0+2)*65 + base] = v2.z; As[2*2080 + (k0+3)*65 + base] = v2.w;
        As[3*2080 + (k0+0)*65 + base] = v3.x; As[3*2080 + (k0+1)*65 + base] = v3.y;
        As[3*2080 + (k0+2)*65 + base] = v3.z; As[3*2080 + (k0+3)*65 + base] = v3.w;
    }
    __syncthreads();
    // ---- stage B: 64 rows x 64 cols; thread = 1 row x 8 cols ----
    {
        int r = tid>>3, tcol = tid&7;
        int nl = r>>2, bb = r&3;
        int n = n0 + nl;
        const float4* gp = (const float4*)(g_gpre + ((t*Bc + bb)*Nc + n)*64 + tcol*8);
        float4 A0 = gp[0], A1 = gp[1];
        float acc[8] = {A0.x,A0.y,A0.z,A0.w,A1.x,A1.y,A1.z,A1.w};
        #pragma unroll
        for(int seg=0; seg<4; seg++){
            const float* Aseg = As + seg*2080;
            #pragma unroll
            for(int k=0;k<32;k++){
                float av = Aseg[k*65 + r];
                const float4* w4 = (const float4*)&Ws[(seg*32+k)*64 + tcol*8];
                float4 w0 = w4[0], w1 = w4[1];
                acc[0]=fmaf(av,w0.x,acc[0]); acc[1]=fmaf(av,w0.y,acc[1]);
                acc[2]=fmaf(av,w0.z,acc[2]); acc[3]=fmaf(av,w0.w,acc[3]);
                acc[4]=fmaf(av,w1.x,acc[4]); acc[5]=fmaf(av,w1.y,acc[5]);
                acc[6]=fmaf(av,w1.z,acc[6]); acc[7]=fmaf(av,w1.w,acc[7]);
            }
        }
        int o0 = tcol*8;
        if(o0 < 32){
            const float4* h4 = (const float4*)(g_h + n*BDc + bb*32 + o0);
            float4 h0 = h4[0], h1 = h4[1];
            float4 r0, r1;
            r0.x = fsig(acc[0])*h0.x; r0.y = fsig(acc[1])*h0.y;
            r0.z = fsig(acc[2])*h0.z; r0.w = fsig(acc[3])*h0.w;
            r1.x = fsig(acc[4])*h1.x; r1.y = fsig(acc[5])*h1.y;
            r1.z = fsig(acc[6])*h1.z; r1.w = fsig(acc[7])*h1.w;
            float4* rh4 = (float4*)(g_rh + n*BDc + bb*32 + o0);
            rh4[0] = r0; rh4[1] = r1;
        }else{
            int oo = o0 - 32;
            float4 u0, u1;
            u0.x = fsig(acc[0]); u0.y = fsig(acc[1]); u0.z = fsig(acc[2]); u0.w = fsig(acc[3]);
            u1.x = fsig(acc[4]); u1.y = fsig(acc[5]); u1.z = fsig(acc[6]); u1.w = fsig(acc[7]);
            float4* u4 = (float4*)(g_u + n*BDc + bb*32 + oo);
            u4[0] = u0; u4[1] = u1;
        }
    }
}

// ---------------- cand: fused z3 hop + GEMM + tanh + GRU update ----------------
__global__ __launch_bounds__(512) void k_cand(int t){
    extern __shared__ float sm[];
    float* Ws = sm;            // 4096 floats
    float* As = sm + 4096;     // 4*2080 floats
    int tid = threadIdx.x;
    int n0 = blockIdx.x*16;
    for(int i=tid;i<4096;i+=512) Ws[i] = g_Wch[i];
    // ---- stage A ----
    {
        int nl = tid>>5, q = tid&31;
        int nn = n0 + nl;
        const float4* r4  = (const float4*)g_rh;
        const float4* y14 = (const float4*)g_y1;
        const float4* y24 = (const float4*)g_y2;
        float4 v0 = r4[nn*32+q];
        float4 v1 = y14[nn*32+q];
        float4 v2 = y24[nn*32+q];
        int cnt = g_ellc[nn];
        const float4* ev4 = (const float4*)(g_ellv + nn*EMAX);
        const int4*   ei4 = (const int4*)(g_elli + nn*EMAX);
        float4 a = {0.f,0.f,0.f,0.f}, b = {0.f,0.f,0.f,0.f};
        int nIt = cnt>>2;
        for(int e4=0; e4<nIt; e4++){
            float4 v = ev4[e4]; int4 ix = ei4[e4];
            float4 x0 = y24[ix.x*32+q];
            float4 x1 = y24[ix.y*32+q];
            float4 x2 = y24[ix.z*32+q];
            float4 x3 = y24[ix.w*32+q];
            a.x=fmaf(v.x,x0.x,a.x); a.y=fmaf(v.x,x0.y,a.y); a.z=fmaf(v.x,x0.z,a.z); a.w=fmaf(v.x,x0.w,a.w);
            b.x=fmaf(v.y,x1.x,b.x); b.y=fmaf(v.y,x1.y,b.y); b.z=fmaf(v.y,x1.z,b.z); b.w=fmaf(v.y,x1.w,b.w);
            a.x=fmaf(v.z,x2.x,a.x); a.y=fmaf(v.z,x2.y,a.y); a.z=fmaf(v.z,x2.z,a.z); a.w=fmaf(v.z,x2.w,a.w);
            b.x=fmaf(v.w,x3.x,b.x); b.y=fmaf(v.w,x3.y,b.y); b.z=fmaf(v.w,x3.z,b.z); b.w=fmaf(v.w,x3.w,b.w);
        }
        for(int e=nIt*4; e<cnt; e++){
            float v = g_ellv[nn*EMAX+e];
            float4 x = y24[g_elli[nn*EMAX+e]*32+q];
            a.x=fmaf(v,x.x,a.x); a.y=fmaf(v,x.y,a.y); a.z=fmaf(v,x.z,a.z); a.w=fmaf(v,x.w,a.w);
        }
        float4 v3;
        v3.x = 2.f*(a.x+b.x) - v1.x;
        v3.y = 2.f*(a.y+b.y) - v1.y;
        v3.z = 2.f*(a.z+b.z) - v1.z;
        v3.w = 2.f*(a.w+b.w) - v1.w;
        int c0 = 4*q;
        int base = nl*4 + (c0>>5);
        int k0 = c0 & 31;
        As[0*2080 + (k0+0)*65 + base] = v0.x; As[0*2080 + (k0+1)*65 + base] = v0.y;
        As[0*2080 + (k0+2)*65 + base] = v0.z; As[0*2080 + (k0+3)*65 + base] = v0.w;
        As[1*2080 + (k0+0)*65 + base] = v1.x; As[1*2080 + (k0+1)*65 + base] = v1.y;
        As[1*2080 + (k0+2)*65 + base] = v1.z; As[1*2080 + (k0+3)*65 + base] = v1.w;
        As[2*2080 + (k0+0)*65 + base] = v2.x; As[2*2080 + (k0+1)*65 + base] = v2.y;
        As[2*2080 + (k0+2)*65 + base] = v2.z; As[2*2080 + (k0+3)*65 + base] = v2.w;
        As[3*2080 + (k0+0)*65 + base] = v3.x; As[3*2080 + (k0+1)*65 + base] = v3.y;
        As[3*2080 + (k0+2)*65 + base] = v3.z; As[3*2080 + (k0+3)*65 + base] = v3.w;
    }
    __syncthreads();
    // ---- stage B: 64 rows x 32 cols; thread = 1 row x 4 cols ----
    {
        int r = tid>>3, tcol = tid&7;
        int nl = r>>2, bb = r&3;
        int n = n0 + nl;
        float4 C0 = *(const float4*)(g_cpre + ((t*Bc + bb)*Nc + n)*32 + tcol*4);
        float acc[4] = {C0.x, C0.y, C0.z, C0.w};
        #pragma unroll
        for(int seg=0; seg<4; seg++){
            const float* Aseg = As + seg*2080;
            #pragma unroll
            for(int k=0;k<32;k++){
                float av = Aseg[k*65 + r];
                float4 w0 = *(const float4*)&Ws[(seg*32+k)*32 + tcol*4];
                acc[0]=fmaf(av,w0.x,acc[0]); acc[1]=fmaf(av,w0.y,acc[1]);
                acc[2]=fmaf(av,w0.z,acc[2]); acc[3]=fmaf(av,w0.w,acc[3]);
            }
        }
        int o0 = tcol*4;
        float4 uu = *(const float4*)(g_u + n*BDc + bb*32 + o0);
        float4 hh = *(const float4*)(g_h + n*BDc + bb*32 + o0);
        float4 hn;
        hn.x = uu.x*hh.x + (1.f-uu.x)*ftanh(acc[0]);
        hn.y = uu.y*hh.y + (1.f-uu.y)*ftanh(acc[1]);
        hn.z = uu.z*hh.z + (1.f-uu.z)*ftanh(acc[2]);
        hn.w = uu.w*hh.w + (1.f-uu.w)*ftanh(acc[3]);
        *(float4*)(g_h + n*BDc + bb*32 + o0) = hn;
    }
}

// ---------------- output head ----------------
__global__ void k_out(const float* __restrict__ W1, const float* __restrict__ b1,
                      const float* __restrict__ W2, const float* __restrict__ b2,
                      float* __restrict__ out){
    int r = blockIdx.x*8 + (threadIdx.x>>5);      // r = b*N + n
    int lane = threadIdx.x & 31;
    int b = r>>11, n = r&2047;
    float hv = g_h[n*BDc + b*Dc + lane];
    float hid = b1[lane];
    #pragma unroll
    for(int j=0;j<32;j++) hid = fmaf(__shfl_sync(0xffffffffu, hv, j), W1[j*32+lane], hid);
    hid = fmaxf(hid, 0.f);
    float o = (lane < Qc) ? b2[lane] : 0.f;
    #pragma unroll
    for(int d=0;d<32;d++){
        float s = __shfl_sync(0xffffffffu, hid, d);
        if(lane < Qc) o = fmaf(s, W2[d*Qc + lane], o);
    }
    if(lane < Qc) out[(b*Qc + lane)*Nc + n] = o;
}

// ---------------- launcher ----------------
extern "C" void kernel_launch(void* const* d_in, const int* in_sizes, int n_in,
                              void* d_out, int out_size){
    const float* X     = (const float*)d_in[0];
    const int*   TE    = (const int*)  d_in[1];
    const float* L     = (const float*)d_in[2];
    const float* SE    = (const float*)d_in[3];
    const float* W_se1 = (const float*)d_in[4];  const float* b_se1 = (const float*)d_in[5];
    const float* W_se2 = (const float*)d_in[6];  const float* b_se2 = (const float*)d_in[7];
    const float* W_te1 = (const float*)d_in[8];  const float* b_te1 = (const float*)d_in[9];
    const float* W_te2 = (const float*)d_in[10]; const float* b_te2 = (const float*)d_in[11];
    const float* W_in1 = (const float*)d_in[12]; const float* b_in1 = (const float*)d_in[13];
    const float* W_in2 = (const float*)d_in[14]; const float* b_in2 = (const float*)d_in[15];
    const float* W_gate= (const float*)d_in[16];
    const float* b_gate= (const float*)d_in[17];
    const float* W_cand= (const float*)d_in[18];
    const float* b_cand= (const float*)d_in[19];
    const float* W_out1= (const float*)d_in[20]; const float* b_out1= (const float*)d_in[21];
    const float* W_out2= (const float*)d_in[22]; const float* b_out2= (const float*)d_in[23];
    float* out = (float*)d_out;

    const int smem_gate = (8192 + 4*2080) * 4;   // 66048 B
    const int smem_cand = (4096 + 4*2080) * 4;   // 49664 B
    cudaFuncSetAttribute(k_gate, cudaFuncAttributeMaxDynamicSharedMemorySize, smem_gate);
    cudaFuncSetAttribute(k_cand, cudaFuncAttributeMaxDynamicSharedMemorySize, smem_cand);

    k_ell<<<Nc/8, 256>>>(L);
    k_pack<<<32, 256>>>(W_gate, W_cand);
    k_se<<<Nc/8, 256>>>(SE, W_se1, b_se1, W_se2, b_se2);
    k_te<<<Bc*(Pc+Qc), 32>>>(TE, W_te1, b_te1, W_te2, b_te2);
    k_xembed<<<(Pc*Bc*Nc)/8, 256>>>(X, W_in1, b_in1, W_in2, b_in2);

    // Chebyshev polys of x for all timesteps (1536 columns)
    k_spmm<<<Nc, 256>>>(0, -1, 1, 1.f);   // X1 = L X0
    k_spmm<<<Nc, 256>>>(1,  0, 2, 2.f);   // X2 = 2 L X1 - X0
    k_spmm<<<Nc, 256>>>(2,  1, 3, 2.f);   // X3 = 2 L X2 - X1

    dim3 pg(32, Pc*Bc);
    k_pre_gate<<<pg, 256>>>(b_gate);
    k_pre_cand<<<pg, 256>>>(b_cand);

    k_step0<<<512, 512>>>();

    for(int t=1; t<Pc; t++){
        k_spmm4<<<256, 256>>>(0, -1, 1, 1.f);   // y1 = L h
        k_spmm4<<<256, 256>>>(1,  0, 2, 2.f);   // y2 = 2 L y1 - h
        k_gate<<<128, 512, smem_gate>>>(t);     // y3 in-tile + gate GEMM + sigmoid
        k_spmm4<<<256, 256>>>(3, -1, 1, 1.f);   // z1 = L rh
        k_spmm4<<<256, 256>>>(1,  3, 2, 2.f);   // z2 = 2 L z1 - rh
        k_cand<<<128, 512, smem_cand>>>(t);     // z3 in-tile + cand GEMM + update
    }

    k_out<<<(Bc*Nc)/8, 256>>>(W_out1, b_out1, W_out2, b_out2, out);
}